// round 12
// baseline (speedup 1.0000x reference)
#include <cuda_runtime.h>
#include <math.h>

#define N_NODES 100000
#define N_EDGES 3200000
#define IN_CH   256
#define HC      128   // HEADS*OUT_CH flattened
#define OUT_CH  64
#define NEG_SLOPE 0.2f

#define SCAN_BLOCK 512
#define N_CHUNKS ((N_NODES + SCAN_BLOCK - 1) / SCAN_BLOCK)   // 196

typedef unsigned long long ull;

// ---------------- scratch ----------------
__device__ float g_x[(size_t)N_NODES * HC];      // projected features, 51.2 MB
__device__ float4 g_att[N_NODES];                // (a_src0, a_src1, a_dst0, a_dst1)
__device__ int g_count[N_NODES];
__device__ int g_offset[N_NODES];
__device__ int g_cursor[N_NODES];
__device__ int g_partial[N_CHUNKS];
__device__ int g_sorted_src[N_EDGES];            // src idx sorted by dst

__device__ __forceinline__ float lrelu(float v) {
    return fmaxf(v, NEG_SLOPE * v);
}

// packed dual-fp32 FMA (sm_103a FFMA2): exact fp32 on both 32-bit lanes
__device__ __forceinline__ ull fma2(ull a, ull b, ull c) {
    ull d;
    asm("fma.rn.f32x2 %0, %1, %2, %3;" : "=l"(d) : "l"(a), "l"(b), "l"(c));
    return d;
}
__device__ __forceinline__ ull pack_dup(float v) {
    unsigned u = __float_as_uint(v);
    return (ull)u | ((ull)u << 32);
}
__device__ __forceinline__ float lo_f(ull p) { return __uint_as_float((unsigned)p); }
__device__ __forceinline__ float hi_f(ull p) { return __uint_as_float((unsigned)(p >> 32)); }

// ---------------- zero counts ----------------
__global__ void zero_counts_kernel() {
    int i = blockIdx.x * blockDim.x + threadIdx.x;
    if (i < N_NODES) g_count[i] = 0;
}

// ------- SGEMM: x = z @ W, FFMA2 inner product, double-buffered smem -------
#define BM 128
#define BN 128
#define BK 16

__global__ __launch_bounds__(256, 2) void gemm_kernel(const float* __restrict__ Z,
                                                      const float* __restrict__ Wm) {
    __shared__ ull   As2[2][BK][BM];  // A value duplicated in both fp32 lanes
    __shared__ float Bs[2][BK][BN];
    int tid = threadIdx.x;
    int row0 = blockIdx.x * BM;

    int a_r = tid >> 2;            // 0..63
    int a_c = (tid & 3) << 2;      // 0,4,8,12
    int b_r = tid >> 5;            // 0..7
    int b_c = (tid & 31) << 2;     // 0..124

    int tx = tid & 15;             // column group
    int ty = tid >> 4;             // row group

    ull acc2[8][4];                // [row][col-pair]; pair j = cols (2j, 2j+1) of float4 halves
#pragma unroll
    for (int i = 0; i < 8; i++)
#pragma unroll
        for (int j = 0; j < 4; j++) acc2[i][j] = 0ull;

    float4 av[2], bv[2];
#pragma unroll
    for (int i = 0; i < 2; i++) {
        int r = row0 + a_r + i * 64;
        av[i] = make_float4(0.f, 0.f, 0.f, 0.f);
        if (r < N_NODES) av[i] = *(const float4*)&Z[(size_t)r * IN_CH + a_c];
        bv[i] = *(const float4*)&Wm[(size_t)(b_r + i * 8) * BN + b_c];
    }
#pragma unroll
    for (int i = 0; i < 2; i++) {
        As2[0][a_c + 0][a_r + i * 64] = pack_dup(av[i].x);
        As2[0][a_c + 1][a_r + i * 64] = pack_dup(av[i].y);
        As2[0][a_c + 2][a_r + i * 64] = pack_dup(av[i].z);
        As2[0][a_c + 3][a_r + i * 64] = pack_dup(av[i].w);
        *(float4*)&Bs[0][b_r + i * 8][b_c] = bv[i];
    }
    __syncthreads();

    const int NK = IN_CH / BK;     // 16
    for (int kt = 0; kt < NK; kt++) {
        int cur = kt & 1;
        int nxt = cur ^ 1;
        if (kt + 1 < NK) {
            int k0 = (kt + 1) * BK;
#pragma unroll
            for (int i = 0; i < 2; i++) {
                int r = row0 + a_r + i * 64;
                av[i] = make_float4(0.f, 0.f, 0.f, 0.f);
                if (r < N_NODES) av[i] = *(const float4*)&Z[(size_t)r * IN_CH + k0 + a_c];
                bv[i] = *(const float4*)&Wm[(size_t)(k0 + b_r + i * 8) * BN + b_c];
            }
        }
#pragma unroll
        for (int k = 0; k < BK; k++) {
            // A: 8 duplicated pairs via 4×16B loads (broadcast across tx lanes)
            longlong2 la0 = *(const longlong2*)&As2[cur][k][ty * 4];
            longlong2 la1 = *(const longlong2*)&As2[cur][k][ty * 4 + 2];
            longlong2 la2 = *(const longlong2*)&As2[cur][k][64 + ty * 4];
            longlong2 la3 = *(const longlong2*)&As2[cur][k][64 + ty * 4 + 2];
            // B: adjacent float pairs are native f32x2 operands (16B-aligned LDS.128)
            longlong2 lb0 = *(const longlong2*)&Bs[cur][k][tx * 4];       // cols tx*4 .. +3
            longlong2 lb1 = *(const longlong2*)&Bs[cur][k][64 + tx * 4];  // cols 64+tx*4 ..
            ull a2[8] = { (ull)la0.x, (ull)la0.y, (ull)la1.x, (ull)la1.y,
                          (ull)la2.x, (ull)la2.y, (ull)la3.x, (ull)la3.y };
            ull b2[4] = { (ull)lb0.x, (ull)lb0.y, (ull)lb1.x, (ull)lb1.y };
#pragma unroll
            for (int i = 0; i < 8; i++)
#pragma unroll
                for (int j = 0; j < 4; j++)
                    acc2[i][j] = fma2(a2[i], b2[j], acc2[i][j]);
        }
        if (kt + 1 < NK) {
#pragma unroll
            for (int i = 0; i < 2; i++) {
                As2[nxt][a_c + 0][a_r + i * 64] = pack_dup(av[i].x);
                As2[nxt][a_c + 1][a_r + i * 64] = pack_dup(av[i].y);
                As2[nxt][a_c + 2][a_r + i * 64] = pack_dup(av[i].z);
                As2[nxt][a_c + 3][a_r + i * 64] = pack_dup(av[i].w);
                *(float4*)&Bs[nxt][b_r + i * 8][b_c] = bv[i];
            }
        }
        __syncthreads();
    }

#pragma unroll
    for (int i = 0; i < 8; i++) {
        int r = row0 + ((i < 4) ? (ty * 4 + i) : (64 + ty * 4 + (i - 4)));
        if (r < N_NODES) {
            float* orow = &g_x[(size_t)r * HC];
            *(float4*)&orow[tx * 4] =
                make_float4(lo_f(acc2[i][0]), hi_f(acc2[i][0]),
                            lo_f(acc2[i][1]), hi_f(acc2[i][1]));
            *(float4*)&orow[64 + tx * 4] =
                make_float4(lo_f(acc2[i][2]), hi_f(acc2[i][2]),
                            lo_f(acc2[i][3]), hi_f(acc2[i][3]));
        }
    }
}

// ---------------- per-node attention dots: a_src / a_dst per head ----------
__global__ void att_kernel(const float* __restrict__ att_src,
                           const float* __restrict__ att_dst) {
    int warp = (blockIdx.x * blockDim.x + threadIdx.x) >> 5;
    if (warp >= N_NODES) return;
    int lane = threadIdx.x & 31;

    float4 xv  = *(const float4*)&g_x[(size_t)warp * HC + lane * 4];
    float4 as4 = __ldg((const float4*)&att_src[lane * 4]);  // flat (H*C)=128
    float4 ad4 = __ldg((const float4*)&att_dst[lane * 4]);

    float ps = xv.x * as4.x + xv.y * as4.y + xv.z * as4.z + xv.w * as4.w;
    float pd = xv.x * ad4.x + xv.y * ad4.y + xv.z * ad4.z + xv.w * ad4.w;
#pragma unroll
    for (int off = 8; off; off >>= 1) {
        ps += __shfl_xor_sync(0xffffffffu, ps, off);
        pd += __shfl_xor_sync(0xffffffffu, pd, off);
    }
    // convergent cross-half shuffles
    float ps16 = __shfl_sync(0xffffffffu, ps, 16);  // head-1 src dot
    float pd16 = __shfl_sync(0xffffffffu, pd, 16);  // head-1 dst dot
    if (lane == 0) {
        g_att[warp] = make_float4(ps, ps16, pd, pd16);
    }
}

// ------- histogram of dst (edge_index int32, row-split [src(E) | dst(E)]) --
__global__ void hist_kernel(const int* __restrict__ ei) {
    int e = blockIdx.x * blockDim.x + threadIdx.x;
    if (e < N_EDGES) {
        int d = __ldg(&ei[N_EDGES + e]);
        if ((unsigned)d < (unsigned)N_NODES)
            atomicAdd(&g_count[d], 1);
    }
}

// ---------- decoupled scan, stage 1: per-chunk sums (196 blocks) ----------
__global__ __launch_bounds__(SCAN_BLOCK) void scan_partial_kernel() {
    __shared__ int sh[SCAN_BLOCK / 32];
    int i = blockIdx.x * SCAN_BLOCK + threadIdx.x;
    int v = (i < N_NODES) ? g_count[i] : 0;
#pragma unroll
    for (int off = 16; off; off >>= 1) v += __shfl_xor_sync(0xffffffffu, v, off);
    int wid = threadIdx.x >> 5;
    if ((threadIdx.x & 31) == 0) sh[wid] = v;
    __syncthreads();
    if (wid == 0) {
        int t = (threadIdx.x < SCAN_BLOCK / 32) ? sh[threadIdx.x] : 0;
#pragma unroll
        for (int off = 8; off; off >>= 1) t += __shfl_xor_sync(0xffffffffu, t, off);
        if (threadIdx.x == 0) g_partial[blockIdx.x] = t;
    }
}

// ---------- stage 2: exclusive scan of 196 partials (1 small block) -------
__global__ __launch_bounds__(256) void scan_top_kernel() {
    __shared__ int sh[256];
    int t = threadIdx.x;
    int v = (t < N_CHUNKS) ? g_partial[t] : 0;
    sh[t] = v;
    __syncthreads();
    for (int off = 1; off < 256; off <<= 1) {
        int u = (t >= off) ? sh[t - off] : 0;
        __syncthreads();
        sh[t] += u;
        __syncthreads();
    }
    if (t < N_CHUNKS) g_partial[t] = sh[t] - v;   // exclusive
}

// ---------- stage 3: local exclusive scan + chunk offset (196 blocks) -----
__global__ __launch_bounds__(SCAN_BLOCK) void scan_final_kernel() {
    __shared__ int sh[SCAN_BLOCK];
    int t = threadIdx.x;
    int i = blockIdx.x * SCAN_BLOCK + t;
    int c = (i < N_NODES) ? g_count[i] : 0;
    sh[t] = c;
    __syncthreads();
    for (int off = 1; off < SCAN_BLOCK; off <<= 1) {
        int u = (t >= off) ? sh[t - off] : 0;
        __syncthreads();
        sh[t] += u;
        __syncthreads();
    }
    if (i < N_NODES) {
        int off = g_partial[blockIdx.x] + sh[t] - c;  // exclusive prefix
        g_offset[i] = off;
        g_cursor[i] = off;
    }
}

// ---------------- counting-sort scatter of src indices ----------------
__global__ void scatter_kernel(const int* __restrict__ ei) {
    int e = blockIdx.x * blockDim.x + threadIdx.x;
    if (e < N_EDGES) {
        int d = __ldg(&ei[N_EDGES + e]);
        int s = __ldg(&ei[e]);
        if ((unsigned)d < (unsigned)N_NODES && (unsigned)s < (unsigned)N_NODES) {
            int pos = atomicAdd(&g_cursor[d], 1);
            g_sorted_src[pos] = s;
        }
    }
}

// ------ aggregation: single pass, un-normalized softmax, 2-way unrolled ----
__global__ __launch_bounds__(256) void aggregate_kernel(const float* __restrict__ bias,
                                                        float* __restrict__ out) {
    int warp = (blockIdx.x * blockDim.x + threadIdx.x) >> 5;
    if (warp >= N_NODES) return;
    int lane = threadIdx.x & 31;
    int d = warp;

    float4 attv = g_att[d];                 // (as0, as1, ad0, ad1)
    int h = lane >> 4;
    float adst = h ? attv.w : attv.z;

    const float4* x4 = (const float4*)g_x;
    const float2* att2 = (const float2*)g_att;

    // self-loop contribution
    float w0 = __expf(lrelu((h ? attv.y : attv.x) + adst));
    float s0 = w0;
    float4 xs = x4[(size_t)d * 32 + lane];
    float4 acc0 = make_float4(w0 * xs.x, w0 * xs.y, w0 * xs.z, w0 * xs.w);
    float s1 = 0.f;
    float4 acc1 = make_float4(0.f, 0.f, 0.f, 0.f);

    int base = g_offset[d];
    int cnt  = g_count[d];

    int i = 0;
    for (; i + 2 <= cnt; i += 2) {
        int sa = g_sorted_src[base + i];
        int sb = g_sorted_src[base + i + 1];
        float2 aa = att2[(size_t)sa * 2];
        float2 ab = att2[(size_t)sb * 2];
        float4 xa = x4[(size_t)sa * 32 + lane];
        float4 xb = x4[(size_t)sb * 32 + lane];

        float wa = __expf(lrelu((h ? aa.y : aa.x) + adst));
        float wb = __expf(lrelu((h ? ab.y : ab.x) + adst));

        s0 += wa;
        acc0.x += wa * xa.x; acc0.y += wa * xa.y;
        acc0.z += wa * xa.z; acc0.w += wa * xa.w;
        s1 += wb;
        acc1.x += wb * xb.x; acc1.y += wb * xb.y;
        acc1.z += wb * xb.z; acc1.w += wb * xb.w;
    }
    if (i < cnt) {
        int sa = g_sorted_src[base + i];
        float2 aa = att2[(size_t)sa * 2];
        float4 xa = x4[(size_t)sa * 32 + lane];
        float wa = __expf(lrelu((h ? aa.y : aa.x) + adst));
        s0 += wa;
        acc0.x += wa * xa.x; acc0.y += wa * xa.y;
        acc0.z += wa * xa.z; acc0.w += wa * xa.w;
    }

    float s = s0 + s1;
    float4 acc = make_float4(acc0.x + acc1.x, acc0.y + acc1.y,
                             acc0.z + acc1.z, acc0.w + acc1.w);

    float inv = 1.0f / (2.0f * s);          // /s then mean over 2 heads
    acc.x *= inv; acc.y *= inv; acc.z *= inv; acc.w *= inv;

    // combine heads: lane j (head0) + lane j+16 (head1)
    float ox = __shfl_down_sync(0xffffffffu, acc.x, 16);
    float oy = __shfl_down_sync(0xffffffffu, acc.y, 16);
    float oz = __shfl_down_sync(0xffffffffu, acc.z, 16);
    float ow = __shfl_down_sync(0xffffffffu, acc.w, 16);
    if (lane < 16) {
        float4 b = __ldg((const float4*)&bias[lane * 4]);
        float4 r = make_float4(acc.x + ox + b.x, acc.y + oy + b.y,
                               acc.z + oz + b.z, acc.w + ow + b.w);
        *(float4*)&out[(size_t)d * OUT_CH + lane * 4] = r;
    }
}

// ---------------- launch ----------------
extern "C" void kernel_launch(void* const* d_in, const int* in_sizes, int n_in,
                              void* d_out, int out_size) {
    const float* z       = (const float*)d_in[0];
    const int*   ei      = (const int*)d_in[1];     // int32, row-split [src(E) | dst(E)]
    const float* Wm      = (const float*)d_in[2];
    const float* att_src = (const float*)d_in[3];
    const float* att_dst = (const float*)d_in[4];
    const float* bias    = (const float*)d_in[5];
    float* out = (float*)d_out;

    zero_counts_kernel<<<(N_NODES + 255) / 256, 256>>>();               // 0
    hist_kernel<<<(N_EDGES + 255) / 256, 256>>>(ei);                    // 1
    scan_partial_kernel<<<N_CHUNKS, SCAN_BLOCK>>>();                    // 2
    gemm_kernel<<<(N_NODES + BM - 1) / BM, 256>>>(z, Wm);               // 3 (profiled)
    scan_top_kernel<<<1, 256>>>();                                      // 4
    scan_final_kernel<<<N_CHUNKS, SCAN_BLOCK>>>();                      // 5
    scatter_kernel<<<(N_EDGES + 255) / 256, 256>>>(ei);                 // 6
    att_kernel<<<(N_NODES * 32 + 255) / 256, 256>>>(att_src, att_dst);  // 7
    aggregate_kernel<<<(N_NODES * 32 + 255) / 256, 256>>>(bias, out);   // 8
}

// round 13
// speedup vs baseline: 1.3692x; 1.3692x over previous
#include <cuda_runtime.h>
#include <cuda_bf16.h>
#include <math.h>

#define N_NODES 100000
#define N_EDGES 3200000
#define IN_CH   256
#define HC      128   // HEADS*OUT_CH flattened
#define OUT_CH  64
#define NEG_SLOPE 0.2f

#define SCAN_BLOCK 512
#define N_CHUNKS ((N_NODES + SCAN_BLOCK - 1) / SCAN_BLOCK)   // 196

// ---------------- scratch ----------------
__device__ float g_x[(size_t)N_NODES * HC];      // projected features, 51.2 MB
__device__ float4 g_att[N_NODES];                // (a_src0, a_src1, a_dst0, a_dst1)
__device__ int g_count[N_NODES];
__device__ int g_offset[N_NODES];
__device__ int g_cursor[N_NODES];
__device__ int g_partial[N_CHUNKS];
__device__ int g_sorted_src[N_EDGES];            // src idx sorted by dst

__device__ __forceinline__ float lrelu(float v) {
    return fmaxf(v, NEG_SLOPE * v);
}

// ---------------- zero counts ----------------
__global__ void zero_counts_kernel() {
    int i = blockIdx.x * blockDim.x + threadIdx.x;
    if (i < N_NODES) g_count[i] = 0;
}

// =================== bf16-split tensor-core GEMM ==========================
// x = z @ W as Ah*Bh + Ah*Bl + Al*Bh (fp32 accumulate), err ~1e-5.
#define BM 128
#define BN 128
#define BK 16
#define AKP 24     // padded A row (ushorts): stride 48B -> conflict-free LDSM
#define BNP 136    // padded B row (ushorts): stride 272B -> conflict-free LDSM

__device__ __forceinline__ unsigned sm_a(const void* p) {
    return (unsigned)__cvta_generic_to_shared(p);
}
__device__ __forceinline__ void ldsm4(unsigned& r0, unsigned& r1, unsigned& r2,
                                      unsigned& r3, unsigned addr) {
    asm volatile("ldmatrix.sync.aligned.m8n8.x4.shared.b16 {%0,%1,%2,%3},[%4];"
                 : "=r"(r0), "=r"(r1), "=r"(r2), "=r"(r3) : "r"(addr));
}
__device__ __forceinline__ void ldsm4t(unsigned& r0, unsigned& r1, unsigned& r2,
                                       unsigned& r3, unsigned addr) {
    asm volatile("ldmatrix.sync.aligned.m8n8.x4.trans.shared.b16 {%0,%1,%2,%3},[%4];"
                 : "=r"(r0), "=r"(r1), "=r"(r2), "=r"(r3) : "r"(addr));
}
__device__ __forceinline__ void mma_bf16(float* c, const unsigned* a,
                                         unsigned b0, unsigned b1) {
    asm volatile(
        "mma.sync.aligned.m16n8k16.row.col.f32.bf16.bf16.f32 "
        "{%0,%1,%2,%3},{%4,%5,%6,%7},{%8,%9},{%0,%1,%2,%3};"
        : "+f"(c[0]), "+f"(c[1]), "+f"(c[2]), "+f"(c[3])
        : "r"(a[0]), "r"(a[1]), "r"(a[2]), "r"(a[3]), "r"(b0), "r"(b1));
}
// split two floats into packed bf16x2 hi and lo words
__device__ __forceinline__ void split2(float x, float y, unsigned& hi, unsigned& lo) {
    __nv_bfloat16 hx = __float2bfloat16_rn(x), hy = __float2bfloat16_rn(y);
    float rx = x - __bfloat162float(hx);
    float ry = y - __bfloat162float(hy);
    __nv_bfloat16 lx = __float2bfloat16_rn(rx), ly = __float2bfloat16_rn(ry);
    hi = (unsigned)__bfloat16_as_ushort(hx) | ((unsigned)__bfloat16_as_ushort(hy) << 16);
    lo = (unsigned)__bfloat16_as_ushort(lx) | ((unsigned)__bfloat16_as_ushort(ly) << 16);
}

__global__ __launch_bounds__(256, 2) void gemm_kernel(const float* __restrict__ Z,
                                                      const float* __restrict__ Wm) {
    __shared__ __align__(16) unsigned short Ah[2][BM][AKP];
    __shared__ __align__(16) unsigned short Al[2][BM][AKP];
    __shared__ __align__(16) unsigned short Bh[2][BK][BNP];
    __shared__ __align__(16) unsigned short Bl[2][BK][BNP];

    int tid = threadIdx.x;
    int lane = tid & 31;
    int wid = tid >> 5;
    int wm = wid & 3;          // 4 warps along M (32 rows each)
    int wn = wid >> 2;         // 2 warps along N (64 cols each)
    int row0 = blockIdx.x * BM;

    // gmem load mapping
    int a_row = tid >> 1;              // 0..127
    int a_kh  = (tid & 1) * 8;         // 0 or 8
    int b_k   = tid >> 4;              // 0..15
    int b_n   = (tid & 15) * 8;        // 0..120

    float acc[2][8][4];
#pragma unroll
    for (int mt = 0; mt < 2; mt++)
#pragma unroll
        for (int nt = 0; nt < 8; nt++)
#pragma unroll
            for (int r = 0; r < 4; r++) acc[mt][nt][r] = 0.f;

    float4 av[2], bv[2];
    // prologue: load tile 0
    {
        int gr = row0 + a_row;
        av[0] = make_float4(0.f, 0.f, 0.f, 0.f);
        av[1] = make_float4(0.f, 0.f, 0.f, 0.f);
        if (gr < N_NODES) {
            av[0] = *(const float4*)&Z[(size_t)gr * IN_CH + a_kh];
            av[1] = *(const float4*)&Z[(size_t)gr * IN_CH + a_kh + 4];
        }
        bv[0] = *(const float4*)&Wm[(size_t)b_k * BN + b_n];
        bv[1] = *(const float4*)&Wm[(size_t)b_k * BN + b_n + 4];
    }
    // convert + store tile 0
    {
        unsigned h, l;
        unsigned* ah = (unsigned*)&Ah[0][a_row][a_kh];
        unsigned* al = (unsigned*)&Al[0][a_row][a_kh];
        split2(av[0].x, av[0].y, h, l); ah[0] = h; al[0] = l;
        split2(av[0].z, av[0].w, h, l); ah[1] = h; al[1] = l;
        split2(av[1].x, av[1].y, h, l); ah[2] = h; al[2] = l;
        split2(av[1].z, av[1].w, h, l); ah[3] = h; al[3] = l;
        unsigned* bh = (unsigned*)&Bh[0][b_k][b_n];
        unsigned* bl = (unsigned*)&Bl[0][b_k][b_n];
        split2(bv[0].x, bv[0].y, h, l); bh[0] = h; bl[0] = l;
        split2(bv[0].z, bv[0].w, h, l); bh[1] = h; bl[1] = l;
        split2(bv[1].x, bv[1].y, h, l); bh[2] = h; bl[2] = l;
        split2(bv[1].z, bv[1].w, h, l); bh[3] = h; bl[3] = l;
    }
    __syncthreads();

    const int NK = IN_CH / BK;   // 16
    for (int kt = 0; kt < NK; kt++) {
        int cur = kt & 1;
        int nxt = cur ^ 1;
        // prefetch next tile to regs
        if (kt + 1 < NK) {
            int k0 = (kt + 1) * BK;
            int gr = row0 + a_row;
            av[0] = make_float4(0.f, 0.f, 0.f, 0.f);
            av[1] = make_float4(0.f, 0.f, 0.f, 0.f);
            if (gr < N_NODES) {
                av[0] = *(const float4*)&Z[(size_t)gr * IN_CH + k0 + a_kh];
                av[1] = *(const float4*)&Z[(size_t)gr * IN_CH + k0 + a_kh + 4];
            }
            bv[0] = *(const float4*)&Wm[(size_t)(k0 + b_k) * BN + b_n];
            bv[1] = *(const float4*)&Wm[(size_t)(k0 + b_k) * BN + b_n + 4];
        }

        // --- compute from buffer cur ---
        unsigned ahf[2][4], alf[2][4];
#pragma unroll
        for (int mt = 0; mt < 2; mt++) {
            int ar = wm * 32 + mt * 16 + (lane & 15);
            int ac = (lane >> 4) * 8;
            ldsm4(ahf[mt][0], ahf[mt][1], ahf[mt][2], ahf[mt][3],
                  sm_a(&Ah[cur][ar][ac]));
            ldsm4(alf[mt][0], alf[mt][1], alf[mt][2], alf[mt][3],
                  sm_a(&Al[cur][ar][ac]));
        }
#pragma unroll
        for (int np = 0; np < 4; np++) {
            unsigned bhf[4], blf[4];
            int br = lane & 15;
            int bc = wn * 64 + np * 16 + (lane >> 4) * 8;
            ldsm4t(bhf[0], bhf[1], bhf[2], bhf[3], sm_a(&Bh[cur][br][bc]));
            ldsm4t(blf[0], blf[1], blf[2], blf[3], sm_a(&Bl[cur][br][bc]));
#pragma unroll
            for (int mt = 0; mt < 2; mt++) {
                mma_bf16(acc[mt][2 * np],     ahf[mt], bhf[0], bhf[1]);
                mma_bf16(acc[mt][2 * np],     ahf[mt], blf[0], blf[1]);
                mma_bf16(acc[mt][2 * np],     alf[mt], bhf[0], bhf[1]);
                mma_bf16(acc[mt][2 * np + 1], ahf[mt], bhf[2], bhf[3]);
                mma_bf16(acc[mt][2 * np + 1], ahf[mt], blf[2], blf[3]);
                mma_bf16(acc[mt][2 * np + 1], alf[mt], bhf[2], bhf[3]);
            }
        }

        // convert + store next tile
        if (kt + 1 < NK) {
            unsigned h, l;
            unsigned* ah = (unsigned*)&Ah[nxt][a_row][a_kh];
            unsigned* al = (unsigned*)&Al[nxt][a_row][a_kh];
            split2(av[0].x, av[0].y, h, l); ah[0] = h; al[0] = l;
            split2(av[0].z, av[0].w, h, l); ah[1] = h; al[1] = l;
            split2(av[1].x, av[1].y, h, l); ah[2] = h; al[2] = l;
            split2(av[1].z, av[1].w, h, l); ah[3] = h; al[3] = l;
            unsigned* bh = (unsigned*)&Bh[nxt][b_k][b_n];
            unsigned* bl = (unsigned*)&Bl[nxt][b_k][b_n];
            split2(bv[0].x, bv[0].y, h, l); bh[0] = h; bl[0] = l;
            split2(bv[0].z, bv[0].w, h, l); bh[1] = h; bl[1] = l;
            split2(bv[1].x, bv[1].y, h, l); bh[2] = h; bl[2] = l;
            split2(bv[1].z, bv[1].w, h, l); bh[3] = h; bl[3] = l;
        }
        __syncthreads();
    }

    // epilogue: acc layout -> g_x
    int g = lane >> 2;
    int q = lane & 3;
#pragma unroll
    for (int mt = 0; mt < 2; mt++) {
#pragma unroll
        for (int nt = 0; nt < 8; nt++) {
            int col = wn * 64 + nt * 8 + q * 2;
            int r1 = row0 + wm * 32 + mt * 16 + g;
            int r2 = r1 + 8;
            if (r1 < N_NODES)
                *(float2*)&g_x[(size_t)r1 * HC + col] =
                    make_float2(acc[mt][nt][0], acc[mt][nt][1]);
            if (r2 < N_NODES)
                *(float2*)&g_x[(size_t)r2 * HC + col] =
                    make_float2(acc[mt][nt][2], acc[mt][nt][3]);
        }
    }
}

// ---------------- per-node attention dots: a_src / a_dst per head ----------
__global__ void att_kernel(const float* __restrict__ att_src,
                           const float* __restrict__ att_dst) {
    int warp = (blockIdx.x * blockDim.x + threadIdx.x) >> 5;
    if (warp >= N_NODES) return;
    int lane = threadIdx.x & 31;

    float4 xv  = *(const float4*)&g_x[(size_t)warp * HC + lane * 4];
    float4 as4 = __ldg((const float4*)&att_src[lane * 4]);  // flat (H*C)=128
    float4 ad4 = __ldg((const float4*)&att_dst[lane * 4]);

    float ps = xv.x * as4.x + xv.y * as4.y + xv.z * as4.z + xv.w * as4.w;
    float pd = xv.x * ad4.x + xv.y * ad4.y + xv.z * ad4.z + xv.w * ad4.w;
#pragma unroll
    for (int off = 8; off; off >>= 1) {
        ps += __shfl_xor_sync(0xffffffffu, ps, off);
        pd += __shfl_xor_sync(0xffffffffu, pd, off);
    }
    float ps16 = __shfl_sync(0xffffffffu, ps, 16);  // head-1 src dot
    float pd16 = __shfl_sync(0xffffffffu, pd, 16);  // head-1 dst dot
    if (lane == 0) {
        g_att[warp] = make_float4(ps, ps16, pd, pd16);
    }
}

// ------- histogram of dst (edge_index int32, row-split [src(E) | dst(E)]) --
__global__ void hist_kernel(const int* __restrict__ ei) {
    int e = blockIdx.x * blockDim.x + threadIdx.x;
    if (e < N_EDGES) {
        int d = __ldg(&ei[N_EDGES + e]);
        if ((unsigned)d < (unsigned)N_NODES)
            atomicAdd(&g_count[d], 1);
    }
}

// ---------- decoupled scan, stage 1: per-chunk sums (196 blocks) ----------
__global__ __launch_bounds__(SCAN_BLOCK) void scan_partial_kernel() {
    __shared__ int sh[SCAN_BLOCK / 32];
    int i = blockIdx.x * SCAN_BLOCK + threadIdx.x;
    int v = (i < N_NODES) ? g_count[i] : 0;
#pragma unroll
    for (int off = 16; off; off >>= 1) v += __shfl_xor_sync(0xffffffffu, v, off);
    int wid = threadIdx.x >> 5;
    if ((threadIdx.x & 31) == 0) sh[wid] = v;
    __syncthreads();
    if (wid == 0) {
        int t = (threadIdx.x < SCAN_BLOCK / 32) ? sh[threadIdx.x] : 0;
#pragma unroll
        for (int off = 8; off; off >>= 1) t += __shfl_xor_sync(0xffffffffu, t, off);
        if (threadIdx.x == 0) g_partial[blockIdx.x] = t;
    }
}

// ---------- stage 2: exclusive scan of 196 partials (1 small block) -------
__global__ __launch_bounds__(256) void scan_top_kernel() {
    __shared__ int sh[256];
    int t = threadIdx.x;
    int v = (t < N_CHUNKS) ? g_partial[t] : 0;
    sh[t] = v;
    __syncthreads();
    for (int off = 1; off < 256; off <<= 1) {
        int u = (t >= off) ? sh[t - off] : 0;
        __syncthreads();
        sh[t] += u;
        __syncthreads();
    }
    if (t < N_CHUNKS) g_partial[t] = sh[t] - v;   // exclusive
}

// ---------- stage 3: local exclusive scan + chunk offset (196 blocks) -----
__global__ __launch_bounds__(SCAN_BLOCK) void scan_final_kernel() {
    __shared__ int sh[SCAN_BLOCK];
    int t = threadIdx.x;
    int i = blockIdx.x * SCAN_BLOCK + t;
    int c = (i < N_NODES) ? g_count[i] : 0;
    sh[t] = c;
    __syncthreads();
    for (int off = 1; off < SCAN_BLOCK; off <<= 1) {
        int u = (t >= off) ? sh[t - off] : 0;
        __syncthreads();
        sh[t] += u;
        __syncthreads();
    }
    if (i < N_NODES) {
        int off = g_partial[blockIdx.x] + sh[t] - c;  // exclusive prefix
        g_offset[i] = off;
        g_cursor[i] = off;
    }
}

// ---------------- counting-sort scatter of src indices ----------------
__global__ void scatter_kernel(const int* __restrict__ ei) {
    int e = blockIdx.x * blockDim.x + threadIdx.x;
    if (e < N_EDGES) {
        int d = __ldg(&ei[N_EDGES + e]);
        int s = __ldg(&ei[e]);
        if ((unsigned)d < (unsigned)N_NODES && (unsigned)s < (unsigned)N_NODES) {
            int pos = atomicAdd(&g_cursor[d], 1);
            g_sorted_src[pos] = s;
        }
    }
}

// ------ aggregation: single pass, un-normalized softmax, 2-way unrolled ----
__global__ __launch_bounds__(256) void aggregate_kernel(const float* __restrict__ bias,
                                                        float* __restrict__ out) {
    int warp = (blockIdx.x * blockDim.x + threadIdx.x) >> 5;
    if (warp >= N_NODES) return;
    int lane = threadIdx.x & 31;
    int d = warp;

    float4 attv = g_att[d];                 // (as0, as1, ad0, ad1)
    int h = lane >> 4;
    float adst = h ? attv.w : attv.z;

    const float4* x4 = (const float4*)g_x;
    const float2* att2 = (const float2*)g_att;

    // self-loop contribution
    float w0 = __expf(lrelu((h ? attv.y : attv.x) + adst));
    float s0 = w0;
    float4 xs = x4[(size_t)d * 32 + lane];
    float4 acc0 = make_float4(w0 * xs.x, w0 * xs.y, w0 * xs.z, w0 * xs.w);
    float s1 = 0.f;
    float4 acc1 = make_float4(0.f, 0.f, 0.f, 0.f);

    int base = g_offset[d];
    int cnt  = g_count[d];

    int i = 0;
    for (; i + 2 <= cnt; i += 2) {
        int sa = g_sorted_src[base + i];
        int sb = g_sorted_src[base + i + 1];
        float2 aa = att2[(size_t)sa * 2];
        float2 ab = att2[(size_t)sb * 2];
        float4 xa = x4[(size_t)sa * 32 + lane];
        float4 xb = x4[(size_t)sb * 32 + lane];

        float wa = __expf(lrelu((h ? aa.y : aa.x) + adst));
        float wb = __expf(lrelu((h ? ab.y : ab.x) + adst));

        s0 += wa;
        acc0.x += wa * xa.x; acc0.y += wa * xa.y;
        acc0.z += wa * xa.z; acc0.w += wa * xa.w;
        s1 += wb;
        acc1.x += wb * xb.x; acc1.y += wb * xb.y;
        acc1.z += wb * xb.z; acc1.w += wb * xb.w;
    }
    if (i < cnt) {
        int sa = g_sorted_src[base + i];
        float2 aa = att2[(size_t)sa * 2];
        float4 xa = x4[(size_t)sa * 32 + lane];
        float wa = __expf(lrelu((h ? aa.y : aa.x) + adst));
        s0 += wa;
        acc0.x += wa * xa.x; acc0.y += wa * xa.y;
        acc0.z += wa * xa.z; acc0.w += wa * xa.w;
    }

    float s = s0 + s1;
    float4 acc = make_float4(acc0.x + acc1.x, acc0.y + acc1.y,
                             acc0.z + acc1.z, acc0.w + acc1.w);

    float inv = 1.0f / (2.0f * s);          // /s then mean over 2 heads
    acc.x *= inv; acc.y *= inv; acc.z *= inv; acc.w *= inv;

    // combine heads: lane j (head0) + lane j+16 (head1)
    float ox = __shfl_down_sync(0xffffffffu, acc.x, 16);
    float oy = __shfl_down_sync(0xffffffffu, acc.y, 16);
    float oz = __shfl_down_sync(0xffffffffu, acc.z, 16);
    float ow = __shfl_down_sync(0xffffffffu, acc.w, 16);
    if (lane < 16) {
        float4 b = __ldg((const float4*)&bias[lane * 4]);
        float4 r = make_float4(acc.x + ox + b.x, acc.y + oy + b.y,
                               acc.z + oz + b.z, acc.w + ow + b.w);
        *(float4*)&out[(size_t)d * OUT_CH + lane * 4] = r;
    }
}

// ---------------- launch ----------------
extern "C" void kernel_launch(void* const* d_in, const int* in_sizes, int n_in,
                              void* d_out, int out_size) {
    const float* z       = (const float*)d_in[0];
    const int*   ei      = (const int*)d_in[1];     // int32, row-split [src(E) | dst(E)]
    const float* Wm      = (const float*)d_in[2];
    const float* att_src = (const float*)d_in[3];
    const float* att_dst = (const float*)d_in[4];
    const float* bias    = (const float*)d_in[5];
    float* out = (float*)d_out;

    zero_counts_kernel<<<(N_NODES + 255) / 256, 256>>>();               // 0
    hist_kernel<<<(N_EDGES + 255) / 256, 256>>>(ei);                    // 1
    scan_partial_kernel<<<N_CHUNKS, SCAN_BLOCK>>>();                    // 2
    gemm_kernel<<<(N_NODES + BM - 1) / BM, 256>>>(z, Wm);               // 3 (profiled)
    scan_top_kernel<<<1, 256>>>();                                      // 4
    scan_final_kernel<<<N_CHUNKS, SCAN_BLOCK>>>();                      // 5
    scatter_kernel<<<(N_EDGES + 255) / 256, 256>>>(ei);                 // 6
    att_kernel<<<(N_NODES * 32 + 255) / 256, 256>>>(att_src, att_dst);  // 7
    aggregate_kernel<<<(N_NODES * 32 + 255) / 256, 256>>>(bias, out);   // 8
}